// round 2
// baseline (speedup 1.0000x reference)
#include <cuda_runtime.h>
#include <math.h>

#define MAXN 100000
#define MAXE 1600000
#define EPS 1e-16f

// ------------------------ scratch (device globals, no allocs) ---------------
__device__ float g_h1[MAXN * 128];     // layer-1 node projections
__device__ float g_out1[MAXN * 128];   // layer-1 unnormalized aggregation
__device__ float g_asrc1[MAXN * 2];
__device__ float g_adst1[MAXN * 2];
__device__ float g_den1[MAXN * 2];     // softmax denominators (unshifted exp)

__device__ float g_h2p[MAXN * 2];      // layer-2 node projections
__device__ float g_asrc2[MAXN];
__device__ float g_adst2[MAXN];
__device__ float g_den2[MAXN];

__device__ float g_weatt1[6];          // [head][k] folded edge-attention weights
__device__ float g_weatt2[3];

// ------------------------ helpers -------------------------------------------
static __device__ __forceinline__ float leaky(float a) { return a > 0.f ? a : 0.2f * a; }

static __device__ __forceinline__ void redAddV4(float* p, float a, float b, float c, float d) {
    asm volatile("red.global.add.v4.f32 [%0], {%1,%2,%3,%4};"
                 :: "l"(p), "f"(a), "f"(b), "f"(c), "f"(d) : "memory");
}
static __device__ __forceinline__ void redAddV2(float* p, float a, float b) {
    asm volatile("red.global.add.v2.f32 [%0], {%1,%2};"
                 :: "l"(p), "f"(a), "f"(b) : "memory");
}
static __device__ __forceinline__ void redAddF(float* p, float a) {
    asm volatile("red.global.add.f32 [%0], %1;" :: "l"(p), "f"(a) : "memory");
}

// ------------------------ K0: fold edge-attention weights -------------------
__global__ void k_pre(const float* __restrict__ We1, const float* __restrict__ ae1,
                      const float* __restrict__ We2, const float* __restrict__ ae2) {
    if (blockIdx.x == 0 && threadIdx.x == 0) {
        for (int h = 0; h < 2; h++)
            for (int k = 0; k < 3; k++) {
                float s = 0.f;
                for (int c = 0; c < 64; c++) s += We1[k * 128 + h * 64 + c] * ae1[h * 64 + c];
                g_weatt1[h * 3 + k] = s;
            }
        for (int k = 0; k < 3; k++)
            g_weatt2[k] = We2[k * 2 + 0] * ae2[0] + We2[k * 2 + 1] * ae2[1];
    }
}

// ------------------------ K1: h1 = x @ W1 (M=N,128x128) ---------------------
#define BM 64
__global__ __launch_bounds__(256) void k_gemm1(const float* __restrict__ x,
                                               const float* __restrict__ W, int N) {
    __shared__ float xs[BM][33];
    __shared__ float ws[32][128];
    const int tid = threadIdx.x;
    const int tx = tid & 31, ty = tid >> 5;
    const int c0 = tx * 4, r0 = ty * 8;
    const int rowBase = blockIdx.x * BM;

    float acc[8][4];
#pragma unroll
    for (int i = 0; i < 8; i++) { acc[i][0] = acc[i][1] = acc[i][2] = acc[i][3] = 0.f; }

    for (int k0 = 0; k0 < 128; k0 += 32) {
        for (int i = tid; i < BM * 32; i += 256) {
            int r = i >> 5, c = i & 31;
            int gr = rowBase + r;
            xs[r][c] = (gr < N) ? x[(long)gr * 128 + k0 + c] : 0.f;
        }
        for (int i = tid; i < 32 * 128 / 4; i += 256) {
            int idx = i * 4;
            int r = idx >> 7, c = idx & 127;
            *(float4*)&ws[r][c] = *(const float4*)&W[(k0 + r) * 128 + c];
        }
        __syncthreads();
#pragma unroll
        for (int kk = 0; kk < 32; kk++) {
            float b0 = ws[kk][c0], b1 = ws[kk][c0 + 1], b2 = ws[kk][c0 + 2], b3 = ws[kk][c0 + 3];
#pragma unroll
            for (int i = 0; i < 8; i++) {
                float a = xs[r0 + i][kk];
                acc[i][0] += a * b0; acc[i][1] += a * b1;
                acc[i][2] += a * b2; acc[i][3] += a * b3;
            }
        }
        __syncthreads();
    }
#pragma unroll
    for (int i = 0; i < 8; i++) {
        int gr = rowBase + r0 + i;
        if (gr < N)
            *(float4*)&g_h1[(long)gr * 128 + c0] =
                make_float4(acc[i][0], acc[i][1], acc[i][2], acc[i][3]);
    }
}

// ------------------------ K2: per-node attention dots (layer 1) -------------
__global__ __launch_bounds__(256) void k_att1(const float* __restrict__ as1,
                                              const float* __restrict__ ad1, int N) {
    int w = (blockIdx.x * blockDim.x + threadIdx.x) >> 5;
    int lane = threadIdx.x & 31;
    if (w >= N) return;
    int c = lane * 4;
    float4 hv = *(const float4*)&g_h1[(long)w * 128 + c];
    float4 s4 = *(const float4*)&as1[c];
    float4 d4 = *(const float4*)&ad1[c];
    float ps = hv.x * s4.x + hv.y * s4.y + hv.z * s4.z + hv.w * s4.w;
    float pd = hv.x * d4.x + hv.y * d4.y + hv.z * d4.z + hv.w * d4.w;
#pragma unroll
    for (int off = 8; off; off >>= 1) {
        ps += __shfl_xor_sync(0xffffffffu, ps, off);
        pd += __shfl_xor_sync(0xffffffffu, pd, off);
    }
    if ((lane & 15) == 0) {
        int h = lane >> 4;
        g_asrc1[w * 2 + h] = ps;
        g_adst1[w * 2 + h] = pd;
    }
}

// ------------------------ K3: init layer-1 (self-loop term) -----------------
// den1 = exp(self alpha); out1 = exp(self alpha) * h1   (unnormalized)
__global__ __launch_bounds__(256) void k_init1(int N) {
    int w = (blockIdx.x * blockDim.x + threadIdx.x) >> 5;
    int lane = threadIdx.x & 31;
    if (w >= N) return;
    int h = lane >> 4;
    float es = __expf(leaky(g_asrc1[w * 2 + h] + g_adst1[w * 2 + h]));
    if ((lane & 15) == 0) g_den1[w * 2 + h] = es;
    int c = lane * 4;
    float4 hv = *(const float4*)&g_h1[(long)w * 128 + c];
    *(float4*)&g_out1[(long)w * 128 + c] =
        make_float4(hv.x * es, hv.y * es, hv.z * es, hv.w * es);
}

// ------------------------ K4: single fused edge pass (layer 1) --------------
// warp per edge: ae = exp(leaky(alpha)); den1[dst] += ae; out1[dst] += ae*h1[src]
__global__ __launch_bounds__(256) void k_edge1(const int* __restrict__ ei,
                                               const float* __restrict__ ea, int E) {
    int w = (blockIdx.x * blockDim.x + threadIdx.x) >> 5;
    if (w >= E) return;
    int lane = threadIdx.x & 31;
    int s = __ldg(&ei[w]), d = __ldg(&ei[E + w]);

    float ae = 0.f;
    if (lane < 2) {  // lane h computes head h
        float e0 = __ldg(&ea[w * 3]), e1 = __ldg(&ea[w * 3 + 1]), e2 = __ldg(&ea[w * 3 + 2]);
        float a = g_asrc1[s * 2 + lane] + g_adst1[d * 2 + lane]
                + e0 * g_weatt1[lane * 3] + e1 * g_weatt1[lane * 3 + 1]
                + e2 * g_weatt1[lane * 3 + 2];
        ae = __expf(leaky(a));
    }
    float ae0 = __shfl_sync(0xffffffffu, ae, 0);
    float ae1 = __shfl_sync(0xffffffffu, ae, 1);
    if (lane == 0) redAddV2(&g_den1[d * 2], ae0, ae1);

    float a = (lane >= 16) ? ae1 : ae0;
    float4 hv = *(const float4*)&g_h1[(long)s * 128 + lane * 4];
    redAddV4(&g_out1[(long)d * 128 + lane * 4], hv.x * a, hv.y * a, hv.z * a, hv.w * a);
}

// ------------------------ K5: normalize + bias + ELU + layer-2 proj ---------
__global__ __launch_bounds__(256) void k_final1(const float* __restrict__ b1,
                                                const float* __restrict__ W2,
                                                const float* __restrict__ as2,
                                                const float* __restrict__ ad2, int N) {
    int w = (blockIdx.x * blockDim.x + threadIdx.x) >> 5;
    int lane = threadIdx.x & 31;
    if (w >= N) return;
    int h = lane >> 4;
    float r = 1.f / (g_den1[w * 2 + h] + EPS);
    int c = lane * 4;
    float4 v = *(const float4*)&g_out1[(long)w * 128 + c];
    v.x = v.x * r + b1[c];     v.y = v.y * r + b1[c + 1];
    v.z = v.z * r + b1[c + 2]; v.w = v.w * r + b1[c + 3];
    v.x = v.x > 0.f ? v.x : expm1f(v.x);
    v.y = v.y > 0.f ? v.y : expm1f(v.y);
    v.z = v.z > 0.f ? v.z : expm1f(v.z);
    v.w = v.w > 0.f ? v.w : expm1f(v.w);
    float p0 = v.x * W2[c * 2]       + v.y * W2[(c + 1) * 2]
             + v.z * W2[(c + 2) * 2] + v.w * W2[(c + 3) * 2];
    float p1 = v.x * W2[c * 2 + 1]       + v.y * W2[(c + 1) * 2 + 1]
             + v.z * W2[(c + 2) * 2 + 1] + v.w * W2[(c + 3) * 2 + 1];
#pragma unroll
    for (int off = 16; off; off >>= 1) {
        p0 += __shfl_xor_sync(0xffffffffu, p0, off);
        p1 += __shfl_xor_sync(0xffffffffu, p1, off);
    }
    if (lane == 0) {
        g_h2p[w * 2] = p0;
        g_h2p[w * 2 + 1] = p1;
        g_asrc2[w] = p0 * as2[0] + p1 * as2[1];
        g_adst2[w] = p0 * ad2[0] + p1 * ad2[1];
    }
}

// ------------------------ K6: init layer-2 (self-loop term) -----------------
__global__ __launch_bounds__(256) void k_init2(float* __restrict__ out, int N) {
    int n = blockIdx.x * blockDim.x + threadIdx.x;
    if (n >= N) return;
    float es = __expf(leaky(g_asrc2[n] + g_adst2[n]));
    g_den2[n] = es;
    float2 hp = *(const float2*)&g_h2p[n * 2];
    out[n * 2]     = hp.x * es;
    out[n * 2 + 1] = hp.y * es;
}

// ------------------------ K7: single fused edge pass (layer 2) --------------
__global__ __launch_bounds__(256) void k_edge2(const int* __restrict__ ei,
                                               const float* __restrict__ ea,
                                               float* __restrict__ out, int E) {
    int e = blockIdx.x * blockDim.x + threadIdx.x;
    if (e >= E) return;
    int s = __ldg(&ei[e]), d = __ldg(&ei[E + e]);
    float a = g_asrc2[s] + g_adst2[d]
            + __ldg(&ea[e * 3])     * g_weatt2[0]
            + __ldg(&ea[e * 3 + 1]) * g_weatt2[1]
            + __ldg(&ea[e * 3 + 2]) * g_weatt2[2];
    float ae = __expf(leaky(a));
    redAddF(&g_den2[d], ae);
    float2 hp = *(const float2*)&g_h2p[s * 2];
    redAddV2(&out[d * 2], hp.x * ae, hp.y * ae);
}

// ------------------------ K8: normalize + bias ------------------------------
__global__ __launch_bounds__(256) void k_final2(float* __restrict__ out,
                                                const float* __restrict__ b2, int N) {
    int n = blockIdx.x * blockDim.x + threadIdx.x;
    if (n >= N) return;
    float r = 1.f / (g_den2[n] + EPS);
    out[n * 2]     = out[n * 2]     * r + b2[0];
    out[n * 2 + 1] = out[n * 2 + 1] * r + b2[1];
}

// ------------------------ launch --------------------------------------------
extern "C" void kernel_launch(void* const* d_in, const int* in_sizes, int n_in,
                              void* d_out, int out_size) {
    const float* x   = (const float*)d_in[0];
    const int*   ei  = (const int*)  d_in[1];
    const float* ea  = (const float*)d_in[2];
    const float* W1  = (const float*)d_in[3];
    const float* We1 = (const float*)d_in[4];
    const float* as1 = (const float*)d_in[5];
    const float* ad1 = (const float*)d_in[6];
    const float* ae1 = (const float*)d_in[7];
    const float* b1  = (const float*)d_in[8];
    const float* W2  = (const float*)d_in[9];
    const float* We2 = (const float*)d_in[10];
    const float* as2 = (const float*)d_in[11];
    const float* ad2 = (const float*)d_in[12];
    const float* ae2 = (const float*)d_in[13];
    const float* b2  = (const float*)d_in[14];
    float* out = (float*)d_out;

    const int N = in_sizes[0] / 128;
    const int E = in_sizes[1] / 2;

    const int T = 256;
    const int gN  = (N + T - 1) / T;            // thread-per-node
    const int gNw = (N * 32 + T - 1) / T;       // warp-per-node
    const int gE  = (E + T - 1) / T;            // thread-per-edge
    const int gEw = (E * 32 + T - 1) / T;       // warp-per-edge
    const int gM  = (N + BM - 1) / BM;

    k_pre<<<1, 128>>>(We1, ae1, We2, ae2);
    k_gemm1<<<gM, 256>>>(x, W1, N);
    k_att1<<<gNw, T>>>(as1, ad1, N);

    k_init1<<<gNw, T>>>(N);
    k_edge1<<<gEw, T>>>(ei, ea, E);
    k_final1<<<gNw, T>>>(b1, W2, as2, ad2, N);

    k_init2<<<gN, T>>>(out, N);
    k_edge2<<<gE, T>>>(ei, ea, out, E);
    k_final2<<<gN, T>>>(out, b2, N);
}

// round 3
// speedup vs baseline: 1.7157x; 1.7157x over previous
#include <cuda_runtime.h>
#include <math.h>

#define MAXN 100000
#define MAXE 1600000
#define EPS 1e-16f

// ------------------------ scratch (device globals, no allocs) ---------------
__device__ float g_h1[MAXN * 128];       // layer-1 node projections
__device__ float g_asrc1[MAXN * 2];
__device__ float g_adst1[MAXN * 2];

__device__ float g_h2p[MAXN * 2];        // layer-2 node projections
__device__ float g_asrc2[MAXN];
__device__ float g_adst2[MAXN];

__device__ float g_weatt1[6];            // [head][k] folded edge-attn weights
__device__ float g_weatt2[3];

// CSR structures (rebuilt every call — deterministic work)
__device__ int  g_deg[MAXN];
__device__ int  g_rowptr[MAXN + 1];
__device__ int  g_cursor[MAXN];
__device__ int  g_blocksum[256];
__device__ int  g_blockoff[256];
__device__ int4 g_csr[MAXE];             // {src, f2i(ae0), f2i(ae1), f2i(edot2)}

// ------------------------ helpers -------------------------------------------
static __device__ __forceinline__ float leaky(float a) { return a > 0.f ? a : 0.2f * a; }

// ------------------------ K0: fold edge-attention weights -------------------
__global__ void k_pre(const float* __restrict__ We1, const float* __restrict__ ae1,
                      const float* __restrict__ We2, const float* __restrict__ ae2) {
    if (blockIdx.x == 0 && threadIdx.x == 0) {
        for (int h = 0; h < 2; h++)
            for (int k = 0; k < 3; k++) {
                float s = 0.f;
                for (int c = 0; c < 64; c++) s += We1[k * 128 + h * 64 + c] * ae1[h * 64 + c];
                g_weatt1[h * 3 + k] = s;
            }
        for (int k = 0; k < 3; k++)
            g_weatt2[k] = We2[k * 2 + 0] * ae2[0] + We2[k * 2 + 1] * ae2[1];
    }
}

// ------------------------ K1: h1 = x @ W1 (N x 128 x 128) -------------------
#define BM 64
__global__ __launch_bounds__(256) void k_gemm1(const float* __restrict__ x,
                                               const float* __restrict__ W, int N) {
    __shared__ float xs[BM][33];
    __shared__ float ws[32][128];
    const int tid = threadIdx.x;
    const int tx = tid & 31, ty = tid >> 5;
    const int c0 = tx * 4, r0 = ty * 8;
    const int rowBase = blockIdx.x * BM;

    float acc[8][4];
#pragma unroll
    for (int i = 0; i < 8; i++) { acc[i][0] = acc[i][1] = acc[i][2] = acc[i][3] = 0.f; }

    for (int k0 = 0; k0 < 128; k0 += 32) {
        for (int i = tid; i < BM * 32; i += 256) {
            int r = i >> 5, c = i & 31;
            int gr = rowBase + r;
            xs[r][c] = (gr < N) ? x[(long)gr * 128 + k0 + c] : 0.f;
        }
        for (int i = tid; i < 32 * 128 / 4; i += 256) {
            int idx = i * 4;
            int r = idx >> 7, c = idx & 127;
            *(float4*)&ws[r][c] = *(const float4*)&W[(k0 + r) * 128 + c];
        }
        __syncthreads();
#pragma unroll
        for (int kk = 0; kk < 32; kk++) {
            float b0 = ws[kk][c0], b1 = ws[kk][c0 + 1], b2 = ws[kk][c0 + 2], b3 = ws[kk][c0 + 3];
#pragma unroll
            for (int i = 0; i < 8; i++) {
                float a = xs[r0 + i][kk];
                acc[i][0] += a * b0; acc[i][1] += a * b1;
                acc[i][2] += a * b2; acc[i][3] += a * b3;
            }
        }
        __syncthreads();
    }
#pragma unroll
    for (int i = 0; i < 8; i++) {
        int gr = rowBase + r0 + i;
        if (gr < N)
            *(float4*)&g_h1[(long)gr * 128 + c0] =
                make_float4(acc[i][0], acc[i][1], acc[i][2], acc[i][3]);
    }
}

// ------------------------ K2: per-node attention dots (layer 1) -------------
__global__ __launch_bounds__(256) void k_att1(const float* __restrict__ as1,
                                              const float* __restrict__ ad1, int N) {
    int w = (blockIdx.x * blockDim.x + threadIdx.x) >> 5;
    int lane = threadIdx.x & 31;
    if (w >= N) return;
    int c = lane * 4;
    float4 hv = *(const float4*)&g_h1[(long)w * 128 + c];
    float4 s4 = *(const float4*)&as1[c];
    float4 d4 = *(const float4*)&ad1[c];
    float ps = hv.x * s4.x + hv.y * s4.y + hv.z * s4.z + hv.w * s4.w;
    float pd = hv.x * d4.x + hv.y * d4.y + hv.z * d4.z + hv.w * d4.w;
#pragma unroll
    for (int off = 8; off; off >>= 1) {
        ps += __shfl_xor_sync(0xffffffffu, ps, off);
        pd += __shfl_xor_sync(0xffffffffu, pd, off);
    }
    if ((lane & 15) == 0) {
        int h = lane >> 4;
        g_asrc1[w * 2 + h] = ps;
        g_adst1[w * 2 + h] = pd;
    }
}

// ------------------------ CSR build ------------------------------------------
__global__ __launch_bounds__(256) void k_zero(int N) {
    int n = blockIdx.x * blockDim.x + threadIdx.x;
    if (n < N) g_deg[n] = 0;
}

__global__ __launch_bounds__(256) void k_hist(const int* __restrict__ ei, int E) {
    int e = blockIdx.x * blockDim.x + threadIdx.x;
    if (e < E) atomicAdd(&g_deg[__ldg(&ei[E + e])], 1);
}

// 2-level exclusive scan: 1024 elems/block (256 thr x 4)
__global__ __launch_bounds__(256) void k_scan1(int N) {
    __shared__ int ssum[256];
    int t = threadIdx.x;
    int base = blockIdx.x * 1024;
    int idx = base + t * 4;
    int v0 = 0, v1 = 0, v2 = 0, v3 = 0;
    if (idx + 3 < N) {
        int4 v = *(const int4*)&g_deg[idx];
        v0 = v.x; v1 = v.y; v2 = v.z; v3 = v.w;
    } else {
        if (idx + 0 < N) v0 = g_deg[idx + 0];
        if (idx + 1 < N) v1 = g_deg[idx + 1];
        if (idx + 2 < N) v2 = g_deg[idx + 2];
        if (idx + 3 < N) v3 = g_deg[idx + 3];
    }
    int s0 = v0, s1 = s0 + v1, s2 = s1 + v2, s3 = s2 + v3;
    ssum[t] = s3;
    __syncthreads();
    for (int off = 1; off < 256; off <<= 1) {
        int add = (t >= off) ? ssum[t - off] : 0;
        __syncthreads();
        ssum[t] += add;
        __syncthreads();
    }
    int texcl = t ? ssum[t - 1] : 0;
    if (idx + 0 < N) g_rowptr[idx + 0] = texcl;
    if (idx + 1 < N) g_rowptr[idx + 1] = texcl + s0;
    if (idx + 2 < N) g_rowptr[idx + 2] = texcl + s1;
    if (idx + 3 < N) g_rowptr[idx + 3] = texcl + s2;
    if (t == 255) g_blocksum[blockIdx.x] = ssum[255];
}

__global__ void k_scan2(int nb, int N) {
    if (threadIdx.x == 0) {
        int run = 0;
        for (int i = 0; i < nb; i++) { g_blockoff[i] = run; run += g_blocksum[i]; }
        g_rowptr[N] = run;   // == E
    }
}

__global__ __launch_bounds__(256) void k_scan3(int N) {
    int n = blockIdx.x * blockDim.x + threadIdx.x;
    if (n >= N) return;
    int v = g_rowptr[n] + g_blockoff[n >> 10];
    g_rowptr[n] = v;
    g_cursor[n] = v;
}

// scatter edges into CSR, precomputing exp(alpha) for layer 1 + edot for layer 2
__global__ __launch_bounds__(256) void k_scatter(const int* __restrict__ ei,
                                                 const float* __restrict__ ea, int E) {
    int e = blockIdx.x * blockDim.x + threadIdx.x;
    if (e >= E) return;
    int s = __ldg(&ei[e]), d = __ldg(&ei[E + e]);
    float e0 = __ldg(&ea[e * 3]), e1 = __ldg(&ea[e * 3 + 1]), e2 = __ldg(&ea[e * 3 + 2]);
    float2 asv = *(const float2*)&g_asrc1[s * 2];
    float2 adv = *(const float2*)&g_adst1[d * 2];
    float ae0 = __expf(leaky(asv.x + adv.x +
                  e0 * g_weatt1[0] + e1 * g_weatt1[1] + e2 * g_weatt1[2]));
    float ae1 = __expf(leaky(asv.y + adv.y +
                  e0 * g_weatt1[3] + e1 * g_weatt1[4] + e2 * g_weatt1[5]));
    float edot2 = e0 * g_weatt2[0] + e1 * g_weatt2[1] + e2 * g_weatt2[2];
    int pos = atomicAdd(&g_cursor[d], 1);
    g_csr[pos] = make_int4(s, __float_as_int(ae0), __float_as_int(ae1), __float_as_int(edot2));
}

// ------------------------ K3: fused layer-1 aggregate + ELU + layer-2 proj --
// one warp per dst node; register accumulation, no atomics
__global__ __launch_bounds__(256) void k_agg1(const float* __restrict__ b1,
                                              const float* __restrict__ W2,
                                              const float* __restrict__ as2,
                                              const float* __restrict__ ad2, int N) {
    int w = (blockIdx.x * blockDim.x + threadIdx.x) >> 5;
    int lane = threadIdx.x & 31;
    if (w >= N) return;
    int beg = g_rowptr[w], end = g_rowptr[w + 1];
    int c = lane * 4;
    int h = lane >> 4;

    // self-loop term (edge features = 0)
    float2 asv = *(const float2*)&g_asrc1[w * 2];
    float2 adv = *(const float2*)&g_adst1[w * 2];
    float den0 = __expf(leaky(asv.x + adv.x));
    float den1 = __expf(leaky(asv.y + adv.y));
    float es = h ? den1 : den0;

    float4 hv = *(const float4*)&g_h1[(long)w * 128 + c];
    float4 acc = make_float4(hv.x * es, hv.y * es, hv.z * es, hv.w * es);

    for (int i0 = beg; i0 < end; i0 += 32) {
        int nthis = min(32, end - i0);
        int4 pl = make_int4(0, 0, 0, 0);
        if (lane < nthis) pl = __ldg(&g_csr[i0 + lane]);
#pragma unroll 4
        for (int j = 0; j < nthis; j++) {
            int   s   = __shfl_sync(0xffffffffu, pl.x, j);
            float ae0 = __int_as_float(__shfl_sync(0xffffffffu, pl.y, j));
            float ae1 = __int_as_float(__shfl_sync(0xffffffffu, pl.z, j));
            den0 += ae0; den1 += ae1;
            float a = h ? ae1 : ae0;
            float4 v = __ldg((const float4*)&g_h1[(long)s * 128 + c]);
            acc.x += v.x * a; acc.y += v.y * a;
            acc.z += v.z * a; acc.w += v.w * a;
        }
    }

    float r = 1.f / ((h ? den1 : den0) + EPS);
    float4 bb = *(const float4*)&b1[c];
    float4 v;
    v.x = acc.x * r + bb.x; v.y = acc.y * r + bb.y;
    v.z = acc.z * r + bb.z; v.w = acc.w * r + bb.w;
    v.x = v.x > 0.f ? v.x : expm1f(v.x);
    v.y = v.y > 0.f ? v.y : expm1f(v.y);
    v.z = v.z > 0.f ? v.z : expm1f(v.z);
    v.w = v.w > 0.f ? v.w : expm1f(v.w);

    // project to layer 2: W2 is [128,2] row-major; lane covers rows c..c+3
    float4 wA = *(const float4*)&W2[lane * 8];       // (W[c,0],W[c,1],W[c+1,0],W[c+1,1])
    float4 wB = *(const float4*)&W2[lane * 8 + 4];   // (W[c+2,0],... )
    float p0 = v.x * wA.x + v.y * wA.z + v.z * wB.x + v.w * wB.z;
    float p1 = v.x * wA.y + v.y * wA.w + v.z * wB.y + v.w * wB.w;
#pragma unroll
    for (int off = 16; off; off >>= 1) {
        p0 += __shfl_xor_sync(0xffffffffu, p0, off);
        p1 += __shfl_xor_sync(0xffffffffu, p1, off);
    }
    if (lane == 0) {
        g_h2p[w * 2]     = p0;
        g_h2p[w * 2 + 1] = p1;
        g_asrc2[w] = p0 * as2[0] + p1 * as2[1];
        g_adst2[w] = p0 * ad2[0] + p1 * ad2[1];
    }
}

// ------------------------ K4: layer-2 aggregate (thread per node) -----------
__global__ __launch_bounds__(256) void k_agg2(float* __restrict__ out,
                                              const float* __restrict__ b2, int N) {
    int n = blockIdx.x * blockDim.x + threadIdx.x;
    if (n >= N) return;
    int beg = g_rowptr[n], end = g_rowptr[n + 1];
    float adn = g_adst2[n];
    float den = __expf(leaky(g_asrc2[n] + adn));
    float2 hp = *(const float2*)&g_h2p[n * 2];
    float a0 = hp.x * den, a1 = hp.y * den;
    for (int i = beg; i < end; i++) {
        int4 pl = __ldg(&g_csr[i]);
        int s = pl.x;
        float edot = __int_as_float(pl.w);
        float ae = __expf(leaky(g_asrc2[s] + adn + edot));
        den += ae;
        float2 hs = *(const float2*)&g_h2p[s * 2];
        a0 += hs.x * ae; a1 += hs.y * ae;
    }
    float r = 1.f / (den + EPS);
    out[n * 2]     = a0 * r + b2[0];
    out[n * 2 + 1] = a1 * r + b2[1];
}

// ------------------------ launch --------------------------------------------
extern "C" void kernel_launch(void* const* d_in, const int* in_sizes, int n_in,
                              void* d_out, int out_size) {
    const float* x   = (const float*)d_in[0];
    const int*   ei  = (const int*)  d_in[1];
    const float* ea  = (const float*)d_in[2];
    const float* W1  = (const float*)d_in[3];
    const float* We1 = (const float*)d_in[4];
    const float* as1 = (const float*)d_in[5];
    const float* ad1 = (const float*)d_in[6];
    const float* ae1 = (const float*)d_in[7];
    const float* b1  = (const float*)d_in[8];
    const float* W2  = (const float*)d_in[9];
    const float* We2 = (const float*)d_in[10];
    const float* as2 = (const float*)d_in[11];
    const float* ad2 = (const float*)d_in[12];
    const float* ae2 = (const float*)d_in[13];
    const float* b2  = (const float*)d_in[14];
    float* out = (float*)d_out;

    const int N = in_sizes[0] / 128;
    const int E = in_sizes[1] / 2;

    const int T = 256;
    const int gN  = (N + T - 1) / T;
    const int gNw = (N * 32 + T - 1) / T;
    const int gE  = (E + T - 1) / T;
    const int gM  = (N + BM - 1) / BM;
    const int nb  = (N + 1023) / 1024;

    k_pre<<<1, 32>>>(We1, ae1, We2, ae2);
    k_gemm1<<<gM, 256>>>(x, W1, N);
    k_att1<<<gNw, T>>>(as1, ad1, N);

    k_zero<<<gN, T>>>(N);
    k_hist<<<gE, T>>>(ei, E);
    k_scan1<<<nb, 256>>>(N);
    k_scan2<<<1, 32>>>(nb, N);
    k_scan3<<<gN, T>>>(N);
    k_scatter<<<gE, T>>>(ei, ea, E);

    k_agg1<<<gNw, T>>>(b1, W2, as2, ad2, N);
    k_agg2<<<gN, T>>>(out, b2, N);
}

// round 5
// speedup vs baseline: 1.8073x; 1.0534x over previous
#include <cuda_runtime.h>
#include <cuda_fp16.h>
#include <math.h>

#define MAXN 100000
#define MAXE 1600000
#define EPS 1e-16f

// ------------------------ scratch (device globals, no allocs) ---------------
__device__ float  g_h1[MAXN * 128];      // layer-1 node projections (fp32)
__device__ __half g_h1h[MAXN * 128];     // fp16 mirror for the gather
__device__ float  g_asrc1[MAXN * 2];
__device__ float  g_adst1[MAXN * 2];

__device__ float g_h2p[MAXN * 2];        // layer-2 node projections
__device__ float g_asrc2[MAXN];
__device__ float g_adst2[MAXN];

__device__ float g_weatt1[6];            // [head][k] folded edge-attn weights
__device__ float g_weatt2[3];

// CSR structures (rebuilt every call — deterministic work)
__device__ int  g_deg[MAXN];
__device__ int  g_rowptr[MAXN + 1];
__device__ int  g_cursor[MAXN];
__device__ int  g_blocksum[256];
__device__ int  g_blockoff[256];
__device__ int4 g_csr[MAXE];             // {src, f2i(ae0), f2i(ae1), f2i(edot2)}

// ------------------------ helpers -------------------------------------------
static __device__ __forceinline__ float leaky(float a) { return a > 0.f ? a : 0.2f * a; }

static __device__ __forceinline__ unsigned h2_bits(__half2 h) {
    union { __half2 h; unsigned u; } cvt;
    cvt.h = h;
    return cvt.u;
}

// ------------------------ K0: fold weights + zero degree histogram ----------
__global__ __launch_bounds__(256) void k_pre_zero(const float* __restrict__ We1,
                                                  const float* __restrict__ ae1,
                                                  const float* __restrict__ We2,
                                                  const float* __restrict__ ae2, int N) {
    int n = blockIdx.x * blockDim.x + threadIdx.x;
    if (n < N) g_deg[n] = 0;
    if (blockIdx.x == 0 && threadIdx.x == 0) {
        for (int h = 0; h < 2; h++)
            for (int k = 0; k < 3; k++) {
                float s = 0.f;
                for (int c = 0; c < 64; c++) s += We1[k * 128 + h * 64 + c] * ae1[h * 64 + c];
                g_weatt1[h * 3 + k] = s;
            }
        for (int k = 0; k < 3; k++)
            g_weatt2[k] = We2[k * 2 + 0] * ae2[0] + We2[k * 2 + 1] * ae2[1];
    }
}

// ------------------------ K1: h1 = x @ W1 (N x 128 x 128) -------------------
#define BM 64
__global__ __launch_bounds__(256) void k_gemm1(const float* __restrict__ x,
                                               const float* __restrict__ W, int N) {
    __shared__ float xs[BM][33];
    __shared__ float ws[32][128];
    const int tid = threadIdx.x;
    const int tx = tid & 31, ty = tid >> 5;
    const int c0 = tx * 4, r0 = ty * 8;
    const int rowBase = blockIdx.x * BM;

    float acc[8][4];
#pragma unroll
    for (int i = 0; i < 8; i++) { acc[i][0] = acc[i][1] = acc[i][2] = acc[i][3] = 0.f; }

    for (int k0 = 0; k0 < 128; k0 += 32) {
        for (int i = tid; i < BM * 32; i += 256) {
            int r = i >> 5, c = i & 31;
            int gr = rowBase + r;
            xs[r][c] = (gr < N) ? x[(long)gr * 128 + k0 + c] : 0.f;
        }
        for (int i = tid; i < 32 * 128 / 4; i += 256) {
            int idx = i * 4;
            int r = idx >> 7, c = idx & 127;
            *(float4*)&ws[r][c] = *(const float4*)&W[(k0 + r) * 128 + c];
        }
        __syncthreads();
#pragma unroll
        for (int kk = 0; kk < 32; kk++) {
            float b0 = ws[kk][c0], b1 = ws[kk][c0 + 1], b2 = ws[kk][c0 + 2], b3 = ws[kk][c0 + 3];
#pragma unroll
            for (int i = 0; i < 8; i++) {
                float a = xs[r0 + i][kk];
                acc[i][0] += a * b0; acc[i][1] += a * b1;
                acc[i][2] += a * b2; acc[i][3] += a * b3;
            }
        }
        __syncthreads();
    }
#pragma unroll
    for (int i = 0; i < 8; i++) {
        int gr = rowBase + r0 + i;
        if (gr < N) {
            *(float4*)&g_h1[(long)gr * 128 + c0] =
                make_float4(acc[i][0], acc[i][1], acc[i][2], acc[i][3]);
            uint2 pk = make_uint2(h2_bits(__floats2half2_rn(acc[i][0], acc[i][1])),
                                  h2_bits(__floats2half2_rn(acc[i][2], acc[i][3])));
            *(uint2*)&g_h1h[(long)gr * 128 + c0] = pk;
        }
    }
}

// ------------------------ K2: per-node attention dots (layer 1) -------------
__global__ __launch_bounds__(256) void k_att1(const float* __restrict__ as1,
                                              const float* __restrict__ ad1, int N) {
    int w = (blockIdx.x * blockDim.x + threadIdx.x) >> 5;
    int lane = threadIdx.x & 31;
    if (w >= N) return;
    int c = lane * 4;
    float4 hv = *(const float4*)&g_h1[(long)w * 128 + c];
    float4 s4 = *(const float4*)&as1[c];
    float4 d4 = *(const float4*)&ad1[c];
    float ps = hv.x * s4.x + hv.y * s4.y + hv.z * s4.z + hv.w * s4.w;
    float pd = hv.x * d4.x + hv.y * d4.y + hv.z * d4.z + hv.w * d4.w;
#pragma unroll
    for (int off = 8; off; off >>= 1) {
        ps += __shfl_xor_sync(0xffffffffu, ps, off);
        pd += __shfl_xor_sync(0xffffffffu, pd, off);
    }
    if ((lane & 15) == 0) {
        int h = lane >> 4;
        g_asrc1[w * 2 + h] = ps;
        g_adst1[w * 2 + h] = pd;
    }
}

// ------------------------ CSR build ------------------------------------------
__global__ __launch_bounds__(256) void k_hist(const int* __restrict__ ei, int E) {
    int e = blockIdx.x * blockDim.x + threadIdx.x;
    if (e < E) atomicAdd(&g_deg[__ldg(&ei[E + e])], 1);
}

// 2-level exclusive scan: 1024 elems/block (256 thr x 4)
__global__ __launch_bounds__(256) void k_scan1(int N) {
    __shared__ int ssum[256];
    int t = threadIdx.x;
    int base = blockIdx.x * 1024;
    int idx = base + t * 4;
    int v0 = 0, v1 = 0, v2 = 0, v3 = 0;
    if (idx + 3 < N) {
        int4 v = *(const int4*)&g_deg[idx];
        v0 = v.x; v1 = v.y; v2 = v.z; v3 = v.w;
    } else {
        if (idx + 0 < N) v0 = g_deg[idx + 0];
        if (idx + 1 < N) v1 = g_deg[idx + 1];
        if (idx + 2 < N) v2 = g_deg[idx + 2];
        if (idx + 3 < N) v3 = g_deg[idx + 3];
    }
    int s0 = v0, s1 = s0 + v1, s2 = s1 + v2, s3 = s2 + v3;
    ssum[t] = s3;
    __syncthreads();
    for (int off = 1; off < 256; off <<= 1) {
        int add = (t >= off) ? ssum[t - off] : 0;
        __syncthreads();
        ssum[t] += add;
        __syncthreads();
    }
    int texcl = t ? ssum[t - 1] : 0;
    if (idx + 0 < N) g_rowptr[idx + 0] = texcl;
    if (idx + 1 < N) g_rowptr[idx + 1] = texcl + s0;
    if (idx + 2 < N) g_rowptr[idx + 2] = texcl + s1;
    if (idx + 3 < N) g_rowptr[idx + 3] = texcl + s2;
    if (t == 255) g_blocksum[blockIdx.x] = ssum[255];
}

__global__ void k_scan2(int nb, int N) {
    if (threadIdx.x == 0) {
        int run = 0;
        for (int i = 0; i < nb; i++) { g_blockoff[i] = run; run += g_blocksum[i]; }
        g_rowptr[N] = run;   // == E
    }
}

__global__ __launch_bounds__(256) void k_scan3(int N) {
    int n = blockIdx.x * blockDim.x + threadIdx.x;
    if (n >= N) return;
    int v = g_rowptr[n] + g_blockoff[n >> 10];
    g_rowptr[n] = v;
    g_cursor[n] = v;
}

// scatter edges into CSR, precomputing exp(alpha) for layer 1 + edot for layer 2
__global__ __launch_bounds__(256) void k_scatter(const int* __restrict__ ei,
                                                 const float* __restrict__ ea, int E) {
    int e = blockIdx.x * blockDim.x + threadIdx.x;
    if (e >= E) return;
    int s = __ldg(&ei[e]), d = __ldg(&ei[E + e]);
    float e0 = __ldg(&ea[e * 3]), e1 = __ldg(&ea[e * 3 + 1]), e2 = __ldg(&ea[e * 3 + 2]);
    float2 asv = *(const float2*)&g_asrc1[s * 2];
    float2 adv = *(const float2*)&g_adst1[d * 2];
    float ae0 = __expf(leaky(asv.x + adv.x +
                  e0 * g_weatt1[0] + e1 * g_weatt1[1] + e2 * g_weatt1[2]));
    float ae1 = __expf(leaky(asv.y + adv.y +
                  e0 * g_weatt1[3] + e1 * g_weatt1[4] + e2 * g_weatt1[5]));
    float edot2 = e0 * g_weatt2[0] + e1 * g_weatt2[1] + e2 * g_weatt2[2];
    int pos = atomicAdd(&g_cursor[d], 1);
    g_csr[pos] = make_int4(s, __float_as_int(ae0), __float_as_int(ae1), __float_as_int(edot2));
}

// ------------------------ K3: fused layer-1 aggregate + ELU + layer-2 proj --
// one warp per dst node; register accumulation, fp16 gather, no atomics
__global__ __launch_bounds__(256) void k_agg1(const float* __restrict__ b1,
                                              const float* __restrict__ W2,
                                              const float* __restrict__ as2,
                                              const float* __restrict__ ad2, int N) {
    int w = (blockIdx.x * blockDim.x + threadIdx.x) >> 5;
    int lane = threadIdx.x & 31;
    if (w >= N) return;
    int beg = g_rowptr[w], end = g_rowptr[w + 1];
    int c = lane * 4;
    int h = lane >> 4;

    // self-loop term (edge features = 0)
    float2 asv = *(const float2*)&g_asrc1[w * 2];
    float2 adv = *(const float2*)&g_adst1[w * 2];
    float den0 = __expf(leaky(asv.x + adv.x));
    float den1 = __expf(leaky(asv.y + adv.y));
    float es = h ? den1 : den0;

    float4 hv = *(const float4*)&g_h1[(long)w * 128 + c];
    float4 acc = make_float4(hv.x * es, hv.y * es, hv.z * es, hv.w * es);

    for (int i0 = beg; i0 < end; i0 += 32) {
        int nthis = min(32, end - i0);
        int4 pl = make_int4(0, 0, 0, 0);
        if (lane < nthis) pl = __ldg(&g_csr[i0 + lane]);
#pragma unroll 4
        for (int j = 0; j < nthis; j++) {
            int   s   = __shfl_sync(0xffffffffu, pl.x, j);
            float ae0 = __int_as_float(__shfl_sync(0xffffffffu, pl.y, j));
            float ae1 = __int_as_float(__shfl_sync(0xffffffffu, pl.z, j));
            den0 += ae0; den1 += ae1;
            float a = h ? ae1 : ae0;
            uint2 pk = __ldg((const uint2*)&g_h1h[(long)s * 128 + c]);
            float2 vlo = __half22float2(*(const __half2*)&pk.x);
            float2 vhi = __half22float2(*(const __half2*)&pk.y);
            acc.x += vlo.x * a; acc.y += vlo.y * a;
            acc.z += vhi.x * a; acc.w += vhi.y * a;
        }
    }

    float r = 1.f / ((h ? den1 : den0) + EPS);
    float4 bb = *(const float4*)&b1[c];
    float4 v;
    v.x = acc.x * r + bb.x; v.y = acc.y * r + bb.y;
    v.z = acc.z * r + bb.z; v.w = acc.w * r + bb.w;
    v.x = v.x > 0.f ? v.x : expm1f(v.x);
    v.y = v.y > 0.f ? v.y : expm1f(v.y);
    v.z = v.z > 0.f ? v.z : expm1f(v.z);
    v.w = v.w > 0.f ? v.w : expm1f(v.w);

    // project to layer 2: W2 is [128,2] row-major; lane covers rows c..c+3
    float4 wA = *(const float4*)&W2[lane * 8];
    float4 wB = *(const float4*)&W2[lane * 8 + 4];
    float p0 = v.x * wA.x + v.y * wA.z + v.z * wB.x + v.w * wB.z;
    float p1 = v.x * wA.y + v.y * wA.w + v.z * wB.y + v.w * wB.w;
#pragma unroll
    for (int off = 16; off; off >>= 1) {
        p0 += __shfl_xor_sync(0xffffffffu, p0, off);
        p1 += __shfl_xor_sync(0xffffffffu, p1, off);
    }
    if (lane == 0) {
        g_h2p[w * 2]     = p0;
        g_h2p[w * 2 + 1] = p1;
        g_asrc2[w] = p0 * as2[0] + p1 * as2[1];
        g_adst2[w] = p0 * ad2[0] + p1 * ad2[1];
    }
}

// ------------------------ K4: layer-2 aggregate (thread per node) -----------
__global__ __launch_bounds__(256) void k_agg2(float* __restrict__ out,
                                              const float* __restrict__ b2, int N) {
    int n = blockIdx.x * blockDim.x + threadIdx.x;
    if (n >= N) return;
    int beg = g_rowptr[n], end = g_rowptr[n + 1];
    float adn = g_adst2[n];
    float den = __expf(leaky(g_asrc2[n] + adn));
    float2 hp = *(const float2*)&g_h2p[n * 2];
    float a0 = hp.x * den, a1 = hp.y * den;
    for (int i = beg; i < end; i++) {
        int4 pl = __ldg(&g_csr[i]);
        int s = pl.x;
        float edot = __int_as_float(pl.w);
        float ae = __expf(leaky(g_asrc2[s] + adn + edot));
        den += ae;
        float2 hs = *(const float2*)&g_h2p[s * 2];
        a0 += hs.x * ae; a1 += hs.y * ae;
    }
    float r = 1.f / (den + EPS);
    out[n * 2]     = a0 * r + b2[0];
    out[n * 2 + 1] = a1 * r + b2[1];
}

// ------------------------ launch --------------------------------------------
extern "C" void kernel_launch(void* const* d_in, const int* in_sizes, int n_in,
                              void* d_out, int out_size) {
    const float* x   = (const float*)d_in[0];
    const int*   ei  = (const int*)  d_in[1];
    const float* ea  = (const float*)d_in[2];
    const float* W1  = (const float*)d_in[3];
    const float* We1 = (const float*)d_in[4];
    const float* as1 = (const float*)d_in[5];
    const float* ad1 = (const float*)d_in[6];
    const float* ae1 = (const float*)d_in[7];
    const float* b1  = (const float*)d_in[8];
    const float* W2  = (const float*)d_in[9];
    const float* We2 = (const float*)d_in[10];
    const float* as2 = (const float*)d_in[11];
    const float* ad2 = (const float*)d_in[12];
    const float* ae2 = (const float*)d_in[13];
    const float* b2  = (const float*)d_in[14];
    float* out = (float*)d_out;

    const int N = in_sizes[0] / 128;
    const int E = in_sizes[1] / 2;

    const int T = 256;
    const int gN  = (N + T - 1) / T;
    const int gNw = (N * 32 + T - 1) / T;
    const int gE  = (E + T - 1) / T;
    const int gM  = (N + BM - 1) / BM;
    const int nb  = (N + 1023) / 1024;

    k_pre_zero<<<gN, T>>>(We1, ae1, We2, ae2, N);
    k_gemm1<<<gM, 256>>>(x, W1, N);
    k_att1<<<gNw, T>>>(as1, ad1, N);

    k_hist<<<gE, T>>>(ei, E);
    k_scan1<<<nb, 256>>>(N);
    k_scan2<<<1, 32>>>(nb, N);
    k_scan3<<<gN, T>>>(N);
    k_scatter<<<gE, T>>>(ei, ea, E);

    k_agg1<<<gNw, T>>>(b1, W2, as2, ad2, N);
    k_agg2<<<gN, T>>>(out, b2, N);
}

// round 6
// speedup vs baseline: 2.0835x; 1.1528x over previous
#include <cuda_runtime.h>
#include <cuda_fp16.h>
#include <math.h>

#define MAXN 100000
#define MAXE 1600000
#define EPS 1e-16f

// ------------------------ scratch (device globals, no allocs) ---------------
__device__ __half g_h1h[MAXN * 128];     // layer-1 node projections (fp16)
__device__ float  g_asrc1[MAXN * 2];
__device__ float  g_adst1[MAXN * 2];

__device__ float g_h2p[MAXN * 2];        // layer-2 node projections
__device__ float g_asrc2[MAXN];
__device__ float g_adst2[MAXN];

__device__ float g_weatt1[6];            // [head][k] folded edge-attn weights
__device__ float g_weatt2[3];

// CSR structures (rebuilt every call — deterministic work)
__device__ int  g_deg[MAXN];
__device__ int  g_rowptr[MAXN + 1];
__device__ int  g_cursor[MAXN];
__device__ int  g_blocksum[256];
__device__ int  g_blockoff[256];
__device__ int4 g_csr[MAXE];             // {src, f2i(ae0), f2i(ae1), f2i(edot2)}

// ------------------------ helpers -------------------------------------------
static __device__ __forceinline__ float leaky(float a) { return a > 0.f ? a : 0.2f * a; }

static __device__ __forceinline__ unsigned h2_bits(__half2 h) {
    union { __half2 h; unsigned u; } cvt;
    cvt.h = h;
    return cvt.u;
}

static __device__ __forceinline__ float to_tf32(float f) {
    float r;
    asm("cvt.rna.tf32.f32 %0, %1;" : "=f"(r) : "f"(f));
    return r;
}

static __device__ __forceinline__ void mma_tf32(float* c, float a0, float a1, float a2,
                                                float a3, float b0, float b1) {
    unsigned ua0 = __float_as_uint(a0), ua1 = __float_as_uint(a1);
    unsigned ua2 = __float_as_uint(a2), ua3 = __float_as_uint(a3);
    unsigned ub0 = __float_as_uint(b0), ub1 = __float_as_uint(b1);
    asm volatile(
        "mma.sync.aligned.m16n8k8.row.col.f32.tf32.tf32.f32 "
        "{%0,%1,%2,%3}, {%4,%5,%6,%7}, {%8,%9}, {%0,%1,%2,%3};"
        : "+f"(c[0]), "+f"(c[1]), "+f"(c[2]), "+f"(c[3])
        : "r"(ua0), "r"(ua1), "r"(ua2), "r"(ua3), "r"(ub0), "r"(ub1));
}

// ------------------------ K0: fold weights + zero degree histogram ----------
__global__ __launch_bounds__(256) void k_pre_zero(const float* __restrict__ We1,
                                                  const float* __restrict__ ae1,
                                                  const float* __restrict__ We2,
                                                  const float* __restrict__ ae2, int N) {
    int n = blockIdx.x * blockDim.x + threadIdx.x;
    if (n < N) g_deg[n] = 0;
    if (blockIdx.x == 0 && threadIdx.x == 0) {
        for (int h = 0; h < 2; h++)
            for (int k = 0; k < 3; k++) {
                float s = 0.f;
                for (int c = 0; c < 64; c++) s += We1[k * 128 + h * 64 + c] * ae1[h * 64 + c];
                g_weatt1[h * 3 + k] = s;
            }
        for (int k = 0; k < 3; k++)
            g_weatt2[k] = We2[k * 2 + 0] * ae2[0] + We2[k * 2 + 1] * ae2[1];
    }
}

// ------------------------ K1: h1 = x @ W1 via tf32 mma + fused att dots -----
// Block: 256 threads (8 warps), tile 128 rows x 128 cols, K=128 in chunks of 32.
#define GBM 128
__global__ __launch_bounds__(256) void k_gemm1(const float* __restrict__ x,
                                               const float* __restrict__ W,
                                               const float* __restrict__ as1,
                                               const float* __restrict__ ad1, int N) {
    __shared__ float xs[GBM][33];    // tf32-rounded x tile
    __shared__ float ws[32][132];    // tf32-rounded W tile
    const int tid = threadIdx.x;
    const int warp = tid >> 5, lane = tid & 31;
    const int lg = lane >> 2;        // group 0..7 (row within fragment)
    const int lt = lane & 3;         // thread in group
    const int rowBase = blockIdx.x * GBM;
    const int wr = warp * 16;        // warp's row offset within tile

    float acc[16][4];
#pragma unroll
    for (int i = 0; i < 16; i++)
        acc[i][0] = acc[i][1] = acc[i][2] = acc[i][3] = 0.f;

    for (int k0 = 0; k0 < 128; k0 += 32) {
        // stage x tile: 128 rows x 32 cols
        for (int i = tid; i < GBM * 8; i += 256) {
            int r = i >> 3, c4 = (i & 7) * 4;
            int gr = rowBase + r;
            float4 v = (gr < N) ? *(const float4*)&x[(long)gr * 128 + k0 + c4]
                                : make_float4(0.f, 0.f, 0.f, 0.f);
            xs[r][c4 + 0] = to_tf32(v.x); xs[r][c4 + 1] = to_tf32(v.y);
            xs[r][c4 + 2] = to_tf32(v.z); xs[r][c4 + 3] = to_tf32(v.w);
        }
        // stage W tile: 32 rows x 128 cols
        for (int i = tid; i < 32 * 32; i += 256) {
            int r = i >> 5, c4 = (i & 31) * 4;
            float4 v = *(const float4*)&W[(long)(k0 + r) * 128 + c4];
            ws[r][c4 + 0] = to_tf32(v.x); ws[r][c4 + 1] = to_tf32(v.y);
            ws[r][c4 + 2] = to_tf32(v.z); ws[r][c4 + 3] = to_tf32(v.w);
        }
        __syncthreads();
#pragma unroll
        for (int kk = 0; kk < 32; kk += 8) {
            int ar = wr + lg, ac = kk + lt;
            float a0 = xs[ar][ac],     a1 = xs[ar + 8][ac];
            float a2 = xs[ar][ac + 4], a3 = xs[ar + 8][ac + 4];
#pragma unroll
            for (int nt = 0; nt < 16; nt++) {
                float b0 = ws[kk + lt][nt * 8 + lg];
                float b1 = ws[kk + 4 + lt][nt * 8 + lg];
                mma_tf32(acc[nt], a0, a1, a2, a3, b0, b1);
            }
        }
        __syncthreads();
    }

    // epilogue: fp16 store + attention dot products
    int rA = rowBase + wr + lg;
    int rB = rA + 8;
    // [row(A/B)][head] src/dst partial dots
    float sA0 = 0.f, sA1 = 0.f, dA0 = 0.f, dA1 = 0.f;
    float sB0 = 0.f, sB1 = 0.f, dB0 = 0.f, dB1 = 0.f;
#pragma unroll
    for (int nt = 0; nt < 16; nt++) {
        int col = nt * 8 + lt * 2;
        if (rA < N)
            *(unsigned*)&g_h1h[(long)rA * 128 + col] =
                h2_bits(__floats2half2_rn(acc[nt][0], acc[nt][1]));
        if (rB < N)
            *(unsigned*)&g_h1h[(long)rB * 128 + col] =
                h2_bits(__floats2half2_rn(acc[nt][2], acc[nt][3]));
        float as0 = __ldg(&as1[col]), as1v = __ldg(&as1[col + 1]);
        float ad0 = __ldg(&ad1[col]), ad1v = __ldg(&ad1[col + 1]);
        if (nt < 8) {
            sA0 += acc[nt][0] * as0 + acc[nt][1] * as1v;
            dA0 += acc[nt][0] * ad0 + acc[nt][1] * ad1v;
            sB0 += acc[nt][2] * as0 + acc[nt][3] * as1v;
            dB0 += acc[nt][2] * ad0 + acc[nt][3] * ad1v;
        } else {
            sA1 += acc[nt][0] * as0 + acc[nt][1] * as1v;
            dA1 += acc[nt][0] * ad0 + acc[nt][1] * ad1v;
            sB1 += acc[nt][2] * as0 + acc[nt][3] * as1v;
            dB1 += acc[nt][2] * ad0 + acc[nt][3] * ad1v;
        }
    }
#pragma unroll
    for (int off = 1; off <= 2; off <<= 1) {
        sA0 += __shfl_xor_sync(0xffffffffu, sA0, off);
        sA1 += __shfl_xor_sync(0xffffffffu, sA1, off);
        dA0 += __shfl_xor_sync(0xffffffffu, dA0, off);
        dA1 += __shfl_xor_sync(0xffffffffu, dA1, off);
        sB0 += __shfl_xor_sync(0xffffffffu, sB0, off);
        sB1 += __shfl_xor_sync(0xffffffffu, sB1, off);
        dB0 += __shfl_xor_sync(0xffffffffu, dB0, off);
        dB1 += __shfl_xor_sync(0xffffffffu, dB1, off);
    }
    if (lt == 0) {
        if (rA < N) {
            g_asrc1[rA * 2] = sA0; g_asrc1[rA * 2 + 1] = sA1;
            g_adst1[rA * 2] = dA0; g_adst1[rA * 2 + 1] = dA1;
        }
        if (rB < N) {
            g_asrc1[rB * 2] = sB0; g_asrc1[rB * 2 + 1] = sB1;
            g_adst1[rB * 2] = dB0; g_adst1[rB * 2 + 1] = dB1;
        }
    }
}

// ------------------------ CSR build ------------------------------------------
__global__ __launch_bounds__(256) void k_hist(const int* __restrict__ ei, int E) {
    int e = blockIdx.x * blockDim.x + threadIdx.x;
    if (e < E) atomicAdd(&g_deg[__ldg(&ei[E + e])], 1);
}

// 2-level exclusive scan: 1024 elems/block (256 thr x 4)
__global__ __launch_bounds__(256) void k_scan1(int N) {
    __shared__ int ssum[256];
    int t = threadIdx.x;
    int base = blockIdx.x * 1024;
    int idx = base + t * 4;
    int v0 = 0, v1 = 0, v2 = 0, v3 = 0;
    if (idx + 3 < N) {
        int4 v = *(const int4*)&g_deg[idx];
        v0 = v.x; v1 = v.y; v2 = v.z; v3 = v.w;
    } else {
        if (idx + 0 < N) v0 = g_deg[idx + 0];
        if (idx + 1 < N) v1 = g_deg[idx + 1];
        if (idx + 2 < N) v2 = g_deg[idx + 2];
        if (idx + 3 < N) v3 = g_deg[idx + 3];
    }
    int s0 = v0, s1 = s0 + v1, s2 = s1 + v2, s3 = s2 + v3;
    ssum[t] = s3;
    __syncthreads();
    for (int off = 1; off < 256; off <<= 1) {
        int add = (t >= off) ? ssum[t - off] : 0;
        __syncthreads();
        ssum[t] += add;
        __syncthreads();
    }
    int texcl = t ? ssum[t - 1] : 0;
    if (idx + 0 < N) g_rowptr[idx + 0] = texcl;
    if (idx + 1 < N) g_rowptr[idx + 1] = texcl + s0;
    if (idx + 2 < N) g_rowptr[idx + 2] = texcl + s1;
    if (idx + 3 < N) g_rowptr[idx + 3] = texcl + s2;
    if (t == 255) g_blocksum[blockIdx.x] = ssum[255];
}

__global__ void k_scan2(int nb, int N) {
    if (threadIdx.x == 0) {
        int run = 0;
        for (int i = 0; i < nb; i++) { g_blockoff[i] = run; run += g_blocksum[i]; }
        g_rowptr[N] = run;   // == E
    }
}

__global__ __launch_bounds__(256) void k_scan3(int N) {
    int n = blockIdx.x * blockDim.x + threadIdx.x;
    if (n >= N) return;
    int v = g_rowptr[n] + g_blockoff[n >> 10];
    g_rowptr[n] = v;
    g_cursor[n] = v;
}

// scatter edges into CSR, precomputing exp(alpha) for layer 1 + edot for layer 2
__global__ __launch_bounds__(256) void k_scatter(const int* __restrict__ ei,
                                                 const float* __restrict__ ea, int E) {
    int e = blockIdx.x * blockDim.x + threadIdx.x;
    if (e >= E) return;
    int s = __ldg(&ei[e]), d = __ldg(&ei[E + e]);
    float e0 = __ldg(&ea[e * 3]), e1 = __ldg(&ea[e * 3 + 1]), e2 = __ldg(&ea[e * 3 + 2]);
    float2 asv = *(const float2*)&g_asrc1[s * 2];
    float2 adv = *(const float2*)&g_adst1[d * 2];
    float ae0 = __expf(leaky(asv.x + adv.x +
                  e0 * g_weatt1[0] + e1 * g_weatt1[1] + e2 * g_weatt1[2]));
    float ae1 = __expf(leaky(asv.y + adv.y +
                  e0 * g_weatt1[3] + e1 * g_weatt1[4] + e2 * g_weatt1[5]));
    float edot2 = e0 * g_weatt2[0] + e1 * g_weatt2[1] + e2 * g_weatt2[2];
    int pos = atomicAdd(&g_cursor[d], 1);
    g_csr[pos] = make_int4(s, __float_as_int(ae0), __float_as_int(ae1), __float_as_int(edot2));
}

// ------------------------ K3: fused layer-1 aggregate + ELU + layer-2 proj --
// one warp per dst node; register accumulation, fp16 gather, no atomics
__global__ __launch_bounds__(256) void k_agg1(const float* __restrict__ b1,
                                              const float* __restrict__ W2,
                                              const float* __restrict__ as2,
                                              const float* __restrict__ ad2, int N) {
    int w = (blockIdx.x * blockDim.x + threadIdx.x) >> 5;
    int lane = threadIdx.x & 31;
    if (w >= N) return;
    int beg = g_rowptr[w], end = g_rowptr[w + 1];
    int c = lane * 4;
    int h = lane >> 4;

    // self-loop term (edge features = 0)
    float2 asv = *(const float2*)&g_asrc1[w * 2];
    float2 adv = *(const float2*)&g_adst1[w * 2];
    float den0 = __expf(leaky(asv.x + adv.x));
    float den1 = __expf(leaky(asv.y + adv.y));
    float es = h ? den1 : den0;

    uint2 pks = *(const uint2*)&g_h1h[(long)w * 128 + c];
    float2 slo = __half22float2(*(const __half2*)&pks.x);
    float2 shi = __half22float2(*(const __half2*)&pks.y);
    float4 acc = make_float4(slo.x * es, slo.y * es, shi.x * es, shi.y * es);

    for (int i0 = beg; i0 < end; i0 += 32) {
        int nthis = min(32, end - i0);
        int4 pl = make_int4(0, 0, 0, 0);
        if (lane < nthis) pl = __ldg(&g_csr[i0 + lane]);
#pragma unroll 4
        for (int j = 0; j < nthis; j++) {
            int   s   = __shfl_sync(0xffffffffu, pl.x, j);
            float ae0 = __int_as_float(__shfl_sync(0xffffffffu, pl.y, j));
            float ae1 = __int_as_float(__shfl_sync(0xffffffffu, pl.z, j));
            den0 += ae0; den1 += ae1;
            float a = h ? ae1 : ae0;
            uint2 pk = __ldg((const uint2*)&g_h1h[(long)s * 128 + c]);
            float2 vlo = __half22float2(*(const __half2*)&pk.x);
            float2 vhi = __half22float2(*(const __half2*)&pk.y);
            acc.x += vlo.x * a; acc.y += vlo.y * a;
            acc.z += vhi.x * a; acc.w += vhi.y * a;
        }
    }

    float r = 1.f / ((h ? den1 : den0) + EPS);
    float4 bb = *(const float4*)&b1[c];
    float4 v;
    v.x = acc.x * r + bb.x; v.y = acc.y * r + bb.y;
    v.z = acc.z * r + bb.z; v.w = acc.w * r + bb.w;
    v.x = v.x > 0.f ? v.x : expm1f(v.x);
    v.y = v.y > 0.f ? v.y : expm1f(v.y);
    v.z = v.z > 0.f ? v.z : expm1f(v.z);
    v.w = v.w > 0.f ? v.w : expm1f(v.w);

    // project to layer 2: W2 is [128,2] row-major; lane covers rows c..c+3
    float4 wA = *(const float4*)&W2[lane * 8];
    float4 wB = *(const float4*)&W2[lane * 8 + 4];
    float p0 = v.x * wA.x + v.y * wA.z + v.z * wB.x + v.w * wB.z;
    float p1 = v.x * wA.y + v.y * wA.w + v.z * wB.y + v.w * wB.w;
#pragma unroll
    for (int off = 16; off; off >>= 1) {
        p0 += __shfl_xor_sync(0xffffffffu, p0, off);
        p1 += __shfl_xor_sync(0xffffffffu, p1, off);
    }
    if (lane == 0) {
        g_h2p[w * 2]     = p0;
        g_h2p[w * 2 + 1] = p1;
        g_asrc2[w] = p0 * as2[0] + p1 * as2[1];
        g_adst2[w] = p0 * ad2[0] + p1 * ad2[1];
    }
}

// ------------------------ K4: layer-2 aggregate (thread per node) -----------
__global__ __launch_bounds__(256) void k_agg2(float* __restrict__ out,
                                              const float* __restrict__ b2, int N) {
    int n = blockIdx.x * blockDim.x + threadIdx.x;
    if (n >= N) return;
    int beg = g_rowptr[n], end = g_rowptr[n + 1];
    float adn = g_adst2[n];
    float den = __expf(leaky(g_asrc2[n] + adn));
    float2 hp = *(const float2*)&g_h2p[n * 2];
    float a0 = hp.x * den, a1 = hp.y * den;
    for (int i = beg; i < end; i++) {
        int4 pl = __ldg(&g_csr[i]);
        int s = pl.x;
        float edot = __int_as_float(pl.w);
        float ae = __expf(leaky(g_asrc2[s] + adn + edot));
        den += ae;
        float2 hs = *(const float2*)&g_h2p[s * 2];
        a0 += hs.x * ae; a1 += hs.y * ae;
    }
    float r = 1.f / (den + EPS);
    out[n * 2]     = a0 * r + b2[0];
    out[n * 2 + 1] = a1 * r + b2[1];
}

// ------------------------ launch --------------------------------------------
extern "C" void kernel_launch(void* const* d_in, const int* in_sizes, int n_in,
                              void* d_out, int out_size) {
    const float* x   = (const float*)d_in[0];
    const int*   ei  = (const int*)  d_in[1];
    const float* ea  = (const float*)d_in[2];
    const float* W1  = (const float*)d_in[3];
    const float* We1 = (const float*)d_in[4];
    const float* as1 = (const float*)d_in[5];
    const float* ad1 = (const float*)d_in[6];
    const float* ae1 = (const float*)d_in[7];
    const float* b1  = (const float*)d_in[8];
    const float* W2  = (const float*)d_in[9];
    const float* We2 = (const float*)d_in[10];
    const float* as2 = (const float*)d_in[11];
    const float* ad2 = (const float*)d_in[12];
    const float* ae2 = (const float*)d_in[13];
    const float* b2  = (const float*)d_in[14];
    float* out = (float*)d_out;

    const int N = in_sizes[0] / 128;
    const int E = in_sizes[1] / 2;

    const int T = 256;
    const int gN  = (N + T - 1) / T;
    const int gNw = (N * 32 + T - 1) / T;
    const int gE  = (E + T - 1) / T;
    const int gM  = (N + GBM - 1) / GBM;
    const int nb  = (N + 1023) / 1024;

    k_pre_zero<<<gN, T>>>(We1, ae1, We2, ae2, N);
    k_gemm1<<<gM, 256>>>(x, W1, as1, ad1, N);

    k_hist<<<gE, T>>>(ei, E);
    k_scan1<<<nb, 256>>>(N);
    k_scan2<<<1, 32>>>(nb, N);
    k_scan3<<<gN, T>>>(N);
    k_scatter<<<gE, T>>>(ei, ea, E);

    k_agg1<<<gNw, T>>>(b1, W2, as2, ad2, N);
    k_agg2<<<gN, T>>>(out, b2, N);
}